// round 16
// baseline (speedup 1.0000x reference)
#include <cuda_runtime.h>
#include <cuda_fp16.h>
#include <math.h>
#include <stdint.h>

// ---------------- problem constants ----------------
#define Bc   8
#define Lc   512
#define Sc   513
#define Dc   1024
#define Hc   16
#define NLc  6
#define FFc  4096
#define NCc  10
#define BSr  (Bc*Sc)          // 4104 token rows
#define OUTN 80
#define HROWS (4*Sc)          // 2052 rows per batch-half

// ---------------- scratch ----------------
__device__ float  g_x[BSr*Dc];
__device__ float  g_proj[BSr*Dc];
__device__ float  g_ff2[BSr*Dc];
__device__ __half g_xh[BSr*Dc];
__device__ __half g_qkvh[BSr*3*Dc];
__device__ __half g_aoh[BSr*Dc];
__device__ __half g_f1h[BSr*FFc];
__device__ __half g_wqh[(size_t)NLc*Dc*3*Dc];
__device__ __half g_woh[(size_t)NLc*Dc*Dc];
__device__ __half g_w1h[(size_t)NLc*Dc*FFc];
__device__ __half g_w2h[(size_t)NLc*FFc*Dc];
__device__ int           g_dpos[Bc*Lc];
__device__ unsigned char g_mask[Bc*Sc];
// CLS tail scratch
__device__ float g_caf[Bc*Dc];
__device__ float g_cxc[Bc*Dc];
__device__ float g_cty[Bc*Dc];
__device__ float g_cth[Bc*FFc];
__device__ float g_cqv[Bc*Dc];

__device__ __forceinline__ float gelu_f(float v) {
    return 0.5f * v * (1.0f + erff(v * 0.7071067811865476f));
}
__device__ __forceinline__ void cp16(void* dst_smem, const void* src, bool p) {
    unsigned int d = (unsigned int)__cvta_generic_to_shared(dst_smem);
    int sz = p ? 16 : 0;
    asm volatile("cp.async.cg.shared.global [%0], [%1], 16, %2;\n"
                 :: "r"(d), "l"(src), "r"(sz));
}
// polynomial e^x for x <= 0 (fma/alu pipes; MUFU-free)
__device__ __forceinline__ float exp_poly(float x) {
    float t = x * 1.4426950408889634f;
    t = fmaxf(t, -126.0f);
    float n = rintf(t);
    float g = (t - n) * 0.6931471805599453f;
    float p = fmaf(g, 1.0f/120.0f, 1.0f/24.0f);
    p = fmaf(p, g, 1.0f/6.0f);
    p = fmaf(p, g, 0.5f);
    p = fmaf(p, g, 1.0f);
    p = fmaf(p, g, 1.0f);
    int e = (int)n;
    float sc = __int_as_float((unsigned)(e + 127) << 23);
    return p * sc;
}

// ---------------- prep ----------------
__global__ void prep_kernel(const int* __restrict__ src,
                            const unsigned char* __restrict__ pad,
                            int* __restrict__ dpos, unsigned char* __restrict__ mask) {
    int b = threadIdx.x;
    if (b >= Bc) return;
    int c = 0;
    for (int j = Lc - 1; j >= 0; j--) {
        if (src[b*Lc + j] < NCc) { dpos[b*Lc + j] = c; c++; }
        else                     { dpos[b*Lc + j] = -1; c = 0; }
    }
    mask[b*Sc] = 0;
    for (int j = 0; j < Lc; j++) mask[b*Sc + 1 + j] = pad[b*Lc + j];
}

// ---------------- weight transpose + fp16 (one layer) ----------------
__global__ void transph(const float* __restrict__ W, __half* __restrict__ Wt,
                        int K, int N) {
    __shared__ float t[32][33];
    int n0 = blockIdx.x*32, k0 = blockIdx.y*32;
    for (int i = threadIdx.y; i < 32; i += 8)
        t[i][threadIdx.x] = W[(size_t)(k0 + i)*N + n0 + threadIdx.x];
    __syncthreads();
    for (int i = threadIdx.y; i < 32; i += 8)
        Wt[(size_t)(n0 + i)*K + k0 + threadIdx.x] = __float2half_rn(t[threadIdx.x][i]);
}

// ---------------- embedding ----------------
__global__ void embed_kernel(const int* __restrict__ src,
                             const float* __restrict__ tok_emb,
                             const float* __restrict__ seq_pos,
                             const float* __restrict__ dig_pos,
                             const float* __restrict__ cls_tok,
                             const int* __restrict__ dpos,
                             float* __restrict__ x, __half* __restrict__ xh, int t0) {
    int t = blockIdx.x + t0;
    int b = t / Sc, s = t % Sc;
    int d4 = threadIdx.x;
    float4 v;
    if (s == 0) {
        v = ((const float4*)cls_tok)[d4];
    } else {
        int tok = src[b*Lc + s - 1];
        float4 a = ((const float4*)(tok_emb + (size_t)tok * Dc))[d4];
        float4 p = ((const float4*)(seq_pos + (size_t)(s - 1) * Dc))[d4];
        v.x = a.x + p.x; v.y = a.y + p.y; v.z = a.z + p.z; v.w = a.w + p.w;
        int dp = dpos[b*Lc + s - 1];
        if (dp >= 0) {
            float4 g = ((const float4*)(dig_pos + (size_t)dp * Dc))[d4];
            v.x += g.x; v.y += g.y; v.z += g.z; v.w += g.w;
        }
    }
    ((float4*)(x + (size_t)t * Dc))[d4] = v;
    __half2* xo = (__half2*)(xh + (size_t)t * Dc);
    xo[d4*2]     = __float22half2_rn(make_float2(v.x, v.y));
    xo[d4*2 + 1] = __float22half2_rn(make_float2(v.z, v.w));
}

// ---------------- fp16 tensor-core GEMM, 2-stage cp.async, 2 CTAs/SM ----------------
// C = A@W^T + bias (+resid) (+gelu); out half or float; output row stride ldc.
#define SAh 72
#define AHSZ (128*SAh)
#define STGH (2*AHSZ)
#define GEMM_SMEM_H (2*STGH*2)

__global__ __launch_bounds__(256, 2) void gemm_h(const __half* __restrict__ A,
                                                 const __half* __restrict__ W,
                                                 const float* __restrict__ bias,
                                                 const float* __restrict__ resid,
                                                 void* __restrict__ Cv,
                                                 int M, int N, int K, int ldc,
                                                 int act, int outh) {
    extern __shared__ __half hsm[];
    int bm = blockIdx.y * 128, bn = blockIdx.x * 128;
    int tid = threadIdx.x;
    int wid = tid >> 5, lane = tid & 31;
    int wm = (wid >> 1) * 32;
    int wn = (wid & 1) * 64;
    int lr = lane >> 2, lc = lane & 3;

    float c[2][8][4];
    #pragma unroll
    for (int mt = 0; mt < 2; mt++)
        #pragma unroll
        for (int nt = 0; nt < 8; nt++)
            #pragma unroll
            for (int i = 0; i < 4; i++) c[mt][nt][i] = 0.f;

    auto load_stage = [&](int s, int k0) {
        __half* Ah = hsm + s * STGH;
        __half* Bh = Ah + AHSZ;
        #pragma unroll
        for (int i = 0; i < 4; i++) {
            int idx = i*256 + tid;
            int r = idx >> 3, cc = idx & 7;
            int gm = bm + r;
            const __half* srcp = A + (size_t)(gm < M ? gm : M-1)*K + k0 + cc*8;
            cp16(&Ah[r*SAh + cc*8], srcp, gm < M);
        }
        #pragma unroll
        for (int i = 0; i < 4; i++) {
            int idx = i*256 + tid;
            int r = idx >> 3, cc = idx & 7;
            cp16(&Bh[r*SAh + cc*8], W + (size_t)(bn + r)*K + k0 + cc*8, true);
        }
    };

    int kT = K / 64;
    load_stage(0, 0);   asm volatile("cp.async.commit_group;\n" ::: "memory");
    load_stage(1, 64);  asm volatile("cp.async.commit_group;\n" ::: "memory");

    for (int t = 0; t < kT; t++) {
        asm volatile("cp.async.wait_group 1;\n" ::: "memory");
        __syncthreads();
        int s = t & 1;
        const __half* Ah = hsm + s * STGH;
        const __half* Bh = Ah + AHSZ;

        #pragma unroll
        for (int kk = 0; kk < 4; kk++) {
            unsigned int af[2][4];
            #pragma unroll
            for (int mt = 0; mt < 2; mt++) {
                int base = (wm + mt*16 + lr)*SAh + kk*16 + 2*lc;
                af[mt][0] = *(const unsigned int*)&Ah[base];
                af[mt][1] = *(const unsigned int*)&Ah[base + 8*SAh];
                af[mt][2] = *(const unsigned int*)&Ah[base + 8];
                af[mt][3] = *(const unsigned int*)&Ah[base + 8*SAh + 8];
            }
            #pragma unroll
            for (int nt = 0; nt < 8; nt++) {
                int bbase = (wn + nt*8 + lr)*SAh + kk*16 + 2*lc;
                unsigned int b0 = *(const unsigned int*)&Bh[bbase];
                unsigned int b1 = *(const unsigned int*)&Bh[bbase + 8];
                #pragma unroll
                for (int mt = 0; mt < 2; mt++) {
                    asm volatile(
                        "mma.sync.aligned.m16n8k16.row.col.f32.f16.f16.f32 "
                        "{%0,%1,%2,%3}, {%4,%5,%6,%7}, {%8,%9}, {%0,%1,%2,%3};"
                        : "+f"(c[mt][nt][0]), "+f"(c[mt][nt][1]),
                          "+f"(c[mt][nt][2]), "+f"(c[mt][nt][3])
                        : "r"(af[mt][0]), "r"(af[mt][1]), "r"(af[mt][2]), "r"(af[mt][3]),
                          "r"(b0), "r"(b1));
                }
            }
        }
        __syncthreads();
        if (t + 2 < kT) load_stage(s, (t + 2) * 64);
        asm volatile("cp.async.commit_group;\n" ::: "memory");
    }

    float*  Cf = (float*)Cv;
    __half* Ch = (__half*)Cv;
    #pragma unroll
    for (int mt = 0; mt < 2; mt++) {
        #pragma unroll
        for (int nt = 0; nt < 8; nt++) {
            int col = bn + wn + nt*8 + lc*2;
            float b0v = bias[col], b1v = bias[col + 1];
            int row0 = bm + wm + mt*16 + lr;
            if (row0 < M) {
                float v0 = c[mt][nt][0] + b0v;
                float v1 = c[mt][nt][1] + b1v;
                if (resid) {
                    float2 rv = *(const float2*)(resid + (size_t)row0*ldc + col);
                    v0 += rv.x; v1 += rv.y;
                }
                if (act) { v0 = gelu_f(v0); v1 = gelu_f(v1); }
                if (outh) *(__half2*)(Ch + (size_t)row0*ldc + col) = __float22half2_rn(make_float2(v0, v1));
                else      *(float2*)(Cf + (size_t)row0*ldc + col) = make_float2(v0, v1);
            }
            int row1 = row0 + 8;
            if (row1 < M) {
                float v2 = c[mt][nt][2] + b0v;
                float v3 = c[mt][nt][3] + b1v;
                if (resid) {
                    float2 rv = *(const float2*)(resid + (size_t)row1*ldc + col);
                    v2 += rv.x; v3 += rv.y;
                }
                if (act) { v2 = gelu_f(v2); v3 = gelu_f(v3); }
                if (outh) *(__half2*)(Ch + (size_t)row1*ldc + col) = __float22half2_rn(make_float2(v2, v3));
                else      *(float2*)(Cf + (size_t)row1*ldc + col) = make_float2(v2, v3);
            }
        }
    }
}

// ---------------- fp16 flash attention: double-buffered cp.async K/V ----------------
#define AS2 72
#define KVT (64*AS2)
#define ATT_SMEM_H (5*KVT*2 + 132*4 + 640)

__global__ __launch_bounds__(128) void attn_h(const __half* __restrict__ qkv,
                                              const float* __restrict__ rel_l,
                                              const unsigned char* __restrict__ mask,
                                              __half* __restrict__ out, int bh0) {
    extern __shared__ __half ash[];
    __half* Qh = ash;
    __half* Kb = Qh + KVT;
    __half* Vb = Kb + 2*KVT;
    float* rel_s = (float*)(Vb + 2*KVT);
    unsigned char* msk = (unsigned char*)(rel_s + 132);

    int bh = blockIdx.y + bh0;
    int b = bh >> 4, h = bh & 15;
    int q0 = blockIdx.x * 64;
    int tid = threadIdx.x;
    int wq = tid >> 5;
    int lane = tid & 31;
    int lr = lane >> 2, lc = lane & 3;
    int r0 = wq*16 + lr;

    for (int i = tid; i < 129; i += 128) rel_s[i] = rel_l[i*Hc + h];
    const unsigned char* mrow = mask + b*Sc;
    for (int i = tid; i < Sc; i += 128) msk[i] = mrow[i];
    for (int i = tid; i < 64*8; i += 128) {
        int q = i >> 3, cc = i & 7;
        int gq = q0 + q;
        uint4 v = make_uint4(0u,0u,0u,0u);
        if (gq < Sc) v = *(const uint4*)(qkv + (size_t)(b*Sc + gq)*3072 + h*64 + cc*8);
        *(uint4*)&Qh[q*AS2 + cc*8] = v;
    }

    auto load_kv = [&](int s, int kt) {
        int k0 = kt * 64;
        __half* Kh = Kb + s*KVT;
        __half* Vh = Vb + s*KVT;
        #pragma unroll
        for (int i2 = 0; i2 < 4; i2++) {
            int i = i2*128 + tid;
            int tok = i >> 3, cc = i & 7;
            int k = k0 + tok;
            int kc = k < Sc ? k : Sc - 1;
            const __half* base = qkv + (size_t)(b*Sc + kc)*3072 + h*64 + cc*8;
            cp16(&Kh[tok*AS2 + cc*8], base + 1024, k < Sc);
            cp16(&Vh[tok*AS2 + cc*8], base + 2048, k < Sc);
        }
    };

    load_kv(0, 0);
    asm volatile("cp.async.commit_group;" ::: "memory");
    __syncthreads();

    unsigned int qf[4][4];
    #pragma unroll
    for (int kk = 0; kk < 4; kk++) {
        int base = r0*AS2 + kk*16 + 2*lc;
        qf[kk][0] = *(const unsigned int*)&Qh[base];
        qf[kk][1] = *(const unsigned int*)&Qh[base + 8*AS2];
        qf[kk][2] = *(const unsigned int*)&Qh[base + 8];
        qf[kk][3] = *(const unsigned int*)&Qh[base + 8*AS2 + 8];
    }

    uint32_t vb0 = (uint32_t)__cvta_generic_to_shared(Vb);
    int vrow = lane & 15;
    int vcol = (lane >> 4) * 8;

    float m0 = -1e30f, m1 = -1e30f, l0 = 0.f, l1 = 0.f;
    float o[8][4];
    #pragma unroll
    for (int nt = 0; nt < 8; nt++)
        #pragma unroll
        for (int i = 0; i < 4; i++) o[nt][i] = 0.f;

    for (int kt = 0; kt < 9; kt++) {
        if (kt + 1 < 9) load_kv((kt + 1) & 1, kt + 1);
        asm volatile("cp.async.commit_group;" ::: "memory");
        if (kt + 1 < 9) asm volatile("cp.async.wait_group 1;" ::: "memory");
        else            asm volatile("cp.async.wait_group 0;" ::: "memory");
        __syncthreads();

        int sbi = kt & 1;
        const __half* Kh = Kb + sbi*KVT;
        uint32_t vbase = vb0 + (uint32_t)(sbi*KVT*2);
        int k0 = kt * 64;

        float s[8][4];
        #pragma unroll
        for (int nt = 0; nt < 8; nt++)
            #pragma unroll
            for (int i = 0; i < 4; i++) s[nt][i] = 0.f;
        #pragma unroll
        for (int kk = 0; kk < 4; kk++) {
            #pragma unroll
            for (int nt = 0; nt < 8; nt++) {
                int bbase = (nt*8 + lr)*AS2 + kk*16 + 2*lc;
                unsigned int b0 = *(const unsigned int*)&Kh[bbase];
                unsigned int b1 = *(const unsigned int*)&Kh[bbase + 8];
                asm volatile(
                    "mma.sync.aligned.m16n8k16.row.col.f32.f16.f16.f32 "
                    "{%0,%1,%2,%3}, {%4,%5,%6,%7}, {%8,%9}, {%0,%1,%2,%3};"
                    : "+f"(s[nt][0]), "+f"(s[nt][1]), "+f"(s[nt][2]), "+f"(s[nt][3])
                    : "r"(qf[kk][0]), "r"(qf[kk][1]), "r"(qf[kk][2]), "r"(qf[kk][3]),
                      "r"(b0), "r"(b1));
            }
        }

        int q_r0 = q0 + r0, q_r1 = q_r0 + 8;
        #pragma unroll
        for (int nt = 0; nt < 8; nt++) {
            #pragma unroll
            for (int j = 0; j < 2; j++) {
                int k = k0 + nt*8 + 2*lc + j;
                bool ok = (k < Sc) && !msk[k < Sc ? k : 0];
                int rr0 = k - q_r0; rr0 = rr0 < -64 ? -64 : (rr0 > 64 ? 64 : rr0);
                int rr1 = k - q_r1; rr1 = rr1 < -64 ? -64 : (rr1 > 64 ? 64 : rr1);
                s[nt][j]   = ok ? fmaf(s[nt][j],   0.125f, rel_s[rr0 + 64]) : -1e30f;
                s[nt][2+j] = ok ? fmaf(s[nt][2+j], 0.125f, rel_s[rr1 + 64]) : -1e30f;
            }
        }

        float mx0 = -1e30f, mx1 = -1e30f;
        #pragma unroll
        for (int nt = 0; nt < 8; nt++) {
            mx0 = fmaxf(mx0, fmaxf(s[nt][0], s[nt][1]));
            mx1 = fmaxf(mx1, fmaxf(s[nt][2], s[nt][3]));
        }
        mx0 = fmaxf(mx0, __shfl_xor_sync(0xffffffffu, mx0, 1));
        mx0 = fmaxf(mx0, __shfl_xor_sync(0xffffffffu, mx0, 2));
        mx1 = fmaxf(mx1, __shfl_xor_sync(0xffffffffu, mx1, 1));
        mx1 = fmaxf(mx1, __shfl_xor_sync(0xffffffffu, mx1, 2));

        float nm0 = fmaxf(m0, mx0), nm1 = fmaxf(m1, mx1);
        float sc0 = __expf(m0 - nm0), sc1 = __expf(m1 - nm1);

        float sum0 = 0.f, sum1 = 0.f;
        #pragma unroll
        for (int nt = 0; nt < 8; nt++) {
            if (nt & 1) {
                s[nt][0] = exp_poly(s[nt][0] - nm0);
                s[nt][1] = exp_poly(s[nt][1] - nm0);
                s[nt][2] = exp_poly(s[nt][2] - nm1);
                s[nt][3] = exp_poly(s[nt][3] - nm1);
            } else {
                s[nt][0] = __expf(s[nt][0] - nm0);
                s[nt][1] = __expf(s[nt][1] - nm0);
                s[nt][2] = __expf(s[nt][2] - nm1);
                s[nt][3] = __expf(s[nt][3] - nm1);
            }
            sum0 += s[nt][0] + s[nt][1];
            sum1 += s[nt][2] + s[nt][3];
        }
        sum0 += __shfl_xor_sync(0xffffffffu, sum0, 1);
        sum0 += __shfl_xor_sync(0xffffffffu, sum0, 2);
        sum1 += __shfl_xor_sync(0xffffffffu, sum1, 1);
        sum1 += __shfl_xor_sync(0xffffffffu, sum1, 2);

        m0 = nm0; m1 = nm1;
        l0 = l0*sc0 + sum0;
        l1 = l1*sc1 + sum1;
        #pragma unroll
        for (int nt = 0; nt < 8; nt++) {
            o[nt][0] *= sc0; o[nt][1] *= sc0;
            o[nt][2] *= sc1; o[nt][3] *= sc1;
        }

        #pragma unroll
        for (int kk = 0; kk < 4; kk++) {
            __half2 a0h = __float22half2_rn(make_float2(s[2*kk][0],   s[2*kk][1]));
            __half2 a1h = __float22half2_rn(make_float2(s[2*kk][2],   s[2*kk][3]));
            __half2 a2h = __float22half2_rn(make_float2(s[2*kk+1][0], s[2*kk+1][1]));
            __half2 a3h = __float22half2_rn(make_float2(s[2*kk+1][2], s[2*kk+1][3]));
            unsigned int a0 = *(unsigned int*)&a0h;
            unsigned int a1 = *(unsigned int*)&a1h;
            unsigned int a2 = *(unsigned int*)&a2h;
            unsigned int a3 = *(unsigned int*)&a3h;
            #pragma unroll
            for (int np = 0; np < 4; np++) {
                unsigned int r0v, r1v, r2v, r3v;
                uint32_t addr = vbase + 2u*((kk*16 + vrow)*AS2 + np*16 + vcol);
                asm volatile(
                    "ldmatrix.sync.aligned.m8n8.x4.trans.shared.b16 {%0,%1,%2,%3}, [%4];"
                    : "=r"(r0v), "=r"(r1v), "=r"(r2v), "=r"(r3v) : "r"(addr));
                asm volatile(
                    "mma.sync.aligned.m16n8k16.row.col.f32.f16.f16.f32 "
                    "{%0,%1,%2,%3}, {%4,%5,%6,%7}, {%8,%9}, {%0,%1,%2,%3};"
                    : "+f"(o[2*np][0]), "+f"(o[2*np][1]), "+f"(o[2*np][2]), "+f"(o[2*np][3])
                    : "r"(a0), "r"(a1), "r"(a2), "r"(a3), "r"(r0v), "r"(r1v));
                asm volatile(
                    "mma.sync.aligned.m16n8k16.row.col.f32.f16.f16.f32 "
                    "{%0,%1,%2,%3}, {%4,%5,%6,%7}, {%8,%9}, {%0,%1,%2,%3};"
                    : "+f"(o[2*np+1][0]), "+f"(o[2*np+1][1]), "+f"(o[2*np+1][2]), "+f"(o[2*np+1][3])
                    : "r"(a0), "r"(a1), "r"(a2), "r"(a3), "r"(r2v), "r"(r3v));
            }
        }
        __syncthreads();
    }

    float inv0 = 1.0f / l0, inv1 = 1.0f / l1;
    int gq0 = q0 + r0, gq1 = gq0 + 8;
    #pragma unroll
    for (int nt = 0; nt < 8; nt++) {
        int col = h*64 + nt*8 + 2*lc;
        if (gq0 < Sc)
            *(__half2*)&out[(size_t)(b*Sc + gq0)*Dc + col] =
                __float22half2_rn(make_float2(o[nt][0]*inv0, o[nt][1]*inv0));
        if (gq1 < Sc)
            *(__half2*)&out[(size_t)(b*Sc + gq1)*Dc + col] =
                __float22half2_rn(make_float2(o[nt][2]*inv1, o[nt][3]*inv1));
    }
}

// ---------------- layernorm: x = LN(in), writes x fp32 and xh fp16 ----------------
__global__ void ln_kernel(const float* __restrict__ in, float* __restrict__ x,
                          const float* __restrict__ g, const float* __restrict__ bta,
                          __half* __restrict__ xh) {
    int row = blockIdx.x;
    int tid = threadIdx.x;
    __shared__ float red[16];
    float4 xv = ((const float4*)(in + (size_t)row*Dc))[tid];
    float s  = xv.x + xv.y + xv.z + xv.w;
    float s2 = xv.x*xv.x + xv.y*xv.y + xv.z*xv.z + xv.w*xv.w;
    #pragma unroll
    for (int o = 16; o; o >>= 1) {
        s  += __shfl_xor_sync(0xffffffffu, s,  o);
        s2 += __shfl_xor_sync(0xffffffffu, s2, o);
    }
    int w = tid >> 5;
    if ((tid & 31) == 0) { red[w] = s; red[8 + w] = s2; }
    __syncthreads();
    float ts = 0.f, ts2 = 0.f;
    #pragma unroll
    for (int i = 0; i < 8; i++) { ts += red[i]; ts2 += red[8 + i]; }
    float mean = ts * (1.0f/Dc);
    float rstd = rsqrtf(ts2 * (1.0f/Dc) - mean*mean + 1e-5f);
    float4 gv = ((const float4*)g)[tid];
    float4 bv = ((const float4*)bta)[tid];
    float4 o;
    o.x = (xv.x - mean)*rstd*gv.x + bv.x;
    o.y = (xv.y - mean)*rstd*gv.y + bv.y;
    o.z = (xv.z - mean)*rstd*gv.z + bv.z;
    o.w = (xv.w - mean)*rstd*gv.w + bv.w;
    ((float4*)(x + (size_t)row*Dc))[tid] = o;
    __half2* xo = (__half2*)(xh + (size_t)row*Dc);
    xo[tid*2]     = __float22half2_rn(make_float2(o.x, o.y));
    xo[tid*2 + 1] = __float22half2_rn(make_float2(o.z, o.w));
}

// ---------------- CLS tail kernels ----------------
__global__ void cls_gatherx(const float* __restrict__ x, float* __restrict__ xc) {
    int b = blockIdx.x, tid = threadIdx.x;
    for (int i = tid; i < Dc; i += 256)
        xc[b*Dc + i] = x[(size_t)(b*Sc)*Dc + i];
}

__global__ void cls_gemm(const float* __restrict__ A, const __half* __restrict__ W,
                         const float* __restrict__ bias, float* __restrict__ Y,
                         int N, int K, int act) {
    __shared__ float As[FFc];
    int b = blockIdx.x;
    int n0 = blockIdx.y * 64;
    int tid = threadIdx.x, wid = tid >> 5, lane = tid & 31;
    for (int i = tid; i < K; i += 256) As[i] = A[b*K + i];
    __syncthreads();
    #pragma unroll
    for (int j = 0; j < 8; j++) {
        int n = n0 + wid*8 + j;
        const __half2* wr = (const __half2*)(W + (size_t)n*K);
        float acc = 0.f;
        for (int k2 = lane; k2 < K/2; k2 += 32) {
            float2 wv = __half22float2(wr[k2]);
            acc = fmaf(As[2*k2], wv.x, acc);
            acc = fmaf(As[2*k2+1], wv.y, acc);
        }
        #pragma unroll
        for (int o = 16; o; o >>= 1) acc += __shfl_xor_sync(0xffffffffu, acc, o);
        if (lane == 0) {
            float v = acc + bias[n];
            if (act) v = gelu_f(v);
            Y[b*N + n] = v;
        }
    }
}

__global__ void cls_attn(const __half* __restrict__ qkv,
                         const float* __restrict__ q8,
                         const float* __restrict__ rel_l,
                         const unsigned char* __restrict__ mask,
                         float* __restrict__ caf) {
    int bh = blockIdx.x;
    int b = bh >> 4, h = bh & 15;
    int tid = threadIdx.x;
    __shared__ float p[520];
    __shared__ float qs[64];
    __shared__ float red[4];
    __shared__ float ob[64];
    if (tid < 64) { qs[tid] = q8[b*Dc + h*64 + tid]; ob[tid] = 0.f; }
    __syncthreads();
    float lm = -1e30f;
    for (int k = tid; k < Sc; k += 128) {
        const __half* kr = qkv + (size_t)(b*Sc + k)*3072 + 1024 + h*64;
        float acc = 0.f;
        #pragma unroll 16
        for (int d = 0; d < 64; d++) acc = fmaf(qs[d], __half2float(kr[d]), acc);
        int rr = k > 64 ? 64 : k;
        float v = -1e30f;
        if (!mask[b*Sc + k]) v = acc*0.125f + rel_l[(rr + 64)*Hc + h];
        p[k] = v;
        lm = fmaxf(lm, v);
    }
    #pragma unroll
    for (int o = 16; o; o >>= 1) lm = fmaxf(lm, __shfl_xor_sync(0xffffffffu, lm, o));
    if ((tid & 31) == 0) red[tid >> 5] = lm;
    __syncthreads();
    float m = fmaxf(fmaxf(red[0], red[1]), fmaxf(red[2], red[3]));
    __syncthreads();
    float ls = 0.f;
    for (int k = tid; k < Sc; k += 128) {
        float e = __expf(p[k] - m);
        p[k] = e;
        ls += e;
    }
    #pragma unroll
    for (int o = 16; o; o >>= 1) ls += __shfl_xor_sync(0xffffffffu, ls, o);
    if ((tid & 31) == 0) red[tid >> 5] = ls;
    __syncthreads();
    float inv = 1.0f / (red[0] + red[1] + red[2] + red[3]);
    int d = tid & 63, hk = tid >> 6;
    float acc = 0.f;
    for (int k = hk; k < Sc; k += 2)
        acc = fmaf(p[k], __half2float(qkv[(size_t)(b*Sc + k)*3072 + 2048 + h*64 + d]), acc);
    atomicAdd(&ob[d], acc);
    __syncthreads();
    if (tid < 64) caf[b*Dc + h*64 + tid] = ob[tid] * inv;
}

__global__ void cls_ln(float* __restrict__ xc, const float* __restrict__ y,
                       const float* __restrict__ g, const float* __restrict__ bta) {
    int b = blockIdx.x, tid = threadIdx.x;
    __shared__ float red[16];
    float4 xv = ((float4*)(xc + b*Dc))[tid];
    float4 yv = ((const float4*)(y + b*Dc))[tid];
    xv.x += yv.x; xv.y += yv.y; xv.z += yv.z; xv.w += yv.w;
    float s  = xv.x + xv.y + xv.z + xv.w;
    float s2 = xv.x*xv.x + xv.y*xv.y + xv.z*xv.z + xv.w*xv.w;
    #pragma unroll
    for (int o = 16; o; o >>= 1) {
        s  += __shfl_xor_sync(0xffffffffu, s,  o);
        s2 += __shfl_xor_sync(0xffffffffu, s2, o);
    }
    int w = tid >> 5;
    if ((tid & 31) == 0) { red[w] = s; red[8 + w] = s2; }
    __syncthreads();
    float ts = 0.f, ts2 = 0.f;
    #pragma unroll
    for (int i = 0; i < 8; i++) { ts += red[i]; ts2 += red[8 + i]; }
    float mean = ts * (1.0f/Dc);
    float rstd = rsqrtf(ts2 * (1.0f/Dc) - mean*mean + 1e-5f);
    float4 gv = ((const float4*)g)[tid];
    float4 bv = ((const float4*)bta)[tid];
    float4 o;
    o.x = (xv.x - mean)*rstd*gv.x + bv.x;
    o.y = (xv.y - mean)*rstd*gv.y + bv.y;
    o.z = (xv.z - mean)*rstd*gv.z + bv.z;
    o.w = (xv.w - mean)*rstd*gv.w + bv.w;
    ((float4*)(xc + b*Dc))[tid] = o;
}

__global__ void cls_final(const float* __restrict__ xc,
                          const float* __restrict__ g, const float* __restrict__ bta,
                          const float* __restrict__ w, const float* __restrict__ cb,
                          float* __restrict__ out) {
    int bb = blockIdx.x;
    const float* row = xc + bb * Dc;
    __shared__ float xn[Dc];
    __shared__ float red[16];
    int tid = threadIdx.x;
    float4 v = ((const float4*)row)[tid];
    float s  = v.x + v.y + v.z + v.w;
    float s2 = v.x*v.x + v.y*v.y + v.z*v.z + v.w*v.w;
    #pragma unroll
    for (int o = 16; o; o >>= 1) {
        s  += __shfl_xor_sync(0xffffffffu, s,  o);
        s2 += __shfl_xor_sync(0xffffffffu, s2, o);
    }
    int wr = tid >> 5;
    if ((tid & 31) == 0) { red[wr] = s; red[8 + wr] = s2; }
    __syncthreads();
    float ts = 0.f, ts2 = 0.f;
    #pragma unroll
    for (int i = 0; i < 8; i++) { ts += red[i]; ts2 += red[8 + i]; }
    float mean = ts * (1.0f/Dc);
    float rstd = rsqrtf(ts2 * (1.0f/Dc) - mean*mean + 1e-5f);
    float4 gv = ((const float4*)g)[tid];
    float4 bv = ((const float4*)bta)[tid];
    xn[tid*4 + 0] = (v.x - mean)*rstd*gv.x + bv.x;
    xn[tid*4 + 1] = (v.y - mean)*rstd*gv.y + bv.y;
    xn[tid*4 + 2] = (v.z - mean)*rstd*gv.z + bv.z;
    xn[tid*4 + 3] = (v.w - mean)*rstd*gv.w + bv.w;
    __syncthreads();
    int wid = tid >> 5, lane = tid & 31;
    for (int n = wid; n < OUTN; n += 8) {
        float a = 0.f;
        for (int k = lane; k < Dc; k += 32) a = fmaf(xn[k], w[(size_t)k*OUTN + n], a);
        #pragma unroll
        for (int o = 16; o; o >>= 1) a += __shfl_xor_sync(0xffffffffu, a, o);
        if (lane == 0) out[bb*OUTN + n] = a + cb[n];
    }
}

// ---------------- launch ----------------
extern "C" void kernel_launch(void* const* d_in, const int* in_sizes, int n_in,
                              void* d_out, int out_size) {
    const int*           src     = (const int*)d_in[0];
    const unsigned char* pad     = (const unsigned char*)d_in[1];
    const float* tok_emb = (const float*)d_in[2];
    const float* seq_pos = (const float*)d_in[3];
    const float* dig_pos = (const float*)d_in[4];
    const float* cls_tok = (const float*)d_in[5];
    const float* qkv_w   = (const float*)d_in[6];
    const float* qkv_b   = (const float*)d_in[7];
    const float* out_w   = (const float*)d_in[8];
    const float* out_b   = (const float*)d_in[9];
    const float* rel     = (const float*)d_in[10];
    const float* ln1g    = (const float*)d_in[11];
    const float* ln1b    = (const float*)d_in[12];
    const float* l1w     = (const float*)d_in[13];
    const float* l1b     = (const float*)d_in[14];
    const float* l2w     = (const float*)d_in[15];
    const float* l2b     = (const float*)d_in[16];
    const float* ln2g    = (const float*)d_in[17];
    const float* ln2b    = (const float*)d_in[18];
    const float* fng     = (const float*)d_in[19];
    const float* fnb     = (const float*)d_in[20];
    const float* clsw    = (const float*)d_in[21];
    const float* clsb    = (const float*)d_in[22];

    float *x, *pr, *f2, *caf, *cxc, *cty, *cth, *cqv;
    __half *xh, *qkvh, *aoh, *f1h, *wqh, *woh, *w1h, *w2h;
    int* dp; unsigned char* mk;
    cudaGetSymbolAddress((void**)&x,   g_x);
    cudaGetSymbolAddress((void**)&pr,  g_proj);
    cudaGetSymbolAddress((void**)&f2,  g_ff2);
    cudaGetSymbolAddress((void**)&xh,  g_xh);
    cudaGetSymbolAddress((void**)&qkvh,g_qkvh);
    cudaGetSymbolAddress((void**)&aoh, g_aoh);
    cudaGetSymbolAddress((void**)&f1h, g_f1h);
    cudaGetSymbolAddress((void**)&wqh, g_wqh);
    cudaGetSymbolAddress((void**)&woh, g_woh);
    cudaGetSymbolAddress((void**)&w1h, g_w1h);
    cudaGetSymbolAddress((void**)&w2h, g_w2h);
    cudaGetSymbolAddress((void**)&dp,  g_dpos);
    cudaGetSymbolAddress((void**)&mk,  g_mask);
    cudaGetSymbolAddress((void**)&caf, g_caf);
    cudaGetSymbolAddress((void**)&cxc, g_cxc);
    cudaGetSymbolAddress((void**)&cty, g_cty);
    cudaGetSymbolAddress((void**)&cth, g_cth);
    cudaGetSymbolAddress((void**)&cqv, g_cqv);

    cudaFuncSetAttribute(gemm_h, cudaFuncAttributeMaxDynamicSharedMemorySize, GEMM_SMEM_H);
    cudaFuncSetAttribute(attn_h, cudaFuncAttributeMaxDynamicSharedMemorySize, ATT_SMEM_H);

    cudaStream_t s2, s3;
    cudaStreamCreateWithFlags(&s2, cudaStreamNonBlocking);
    cudaStreamCreateWithFlags(&s3, cudaStreamNonBlocking);
    cudaEvent_t e0, ePrep, eLn1, eD1;
    cudaEvent_t evW[NLc];
    cudaEventCreateWithFlags(&e0,    cudaEventDisableTiming);
    cudaEventCreateWithFlags(&ePrep, cudaEventDisableTiming);
    cudaEventCreateWithFlags(&eLn1,  cudaEventDisableTiming);
    cudaEventCreateWithFlags(&eD1,   cudaEventDisableTiming);
    for (int l = 0; l < NLc; l++) cudaEventCreateWithFlags(&evW[l], cudaEventDisableTiming);

    cudaEventRecord(e0, 0);
    cudaStreamWaitEvent(s3, e0, 0);
    cudaStreamWaitEvent(s2, e0, 0);
    for (int l = 0; l < NLc; l++) {
        transph<<<dim3(3*Dc/32, Dc/32), dim3(32,8), 0, s3>>>(
            qkv_w + (size_t)l*Dc*3*Dc, wqh + (size_t)l*Dc*3*Dc, Dc, 3*Dc);
        transph<<<dim3(Dc/32, Dc/32), dim3(32,8), 0, s3>>>(
            out_w + (size_t)l*Dc*Dc, woh + (size_t)l*Dc*Dc, Dc, Dc);
        transph<<<dim3(FFc/32, Dc/32), dim3(32,8), 0, s3>>>(
            l1w + (size_t)l*Dc*FFc, w1h + (size_t)l*Dc*FFc, Dc, FFc);
        transph<<<dim3(Dc/32, FFc/32), dim3(32,8), 0, s3>>>(
            l2w + (size_t)l*FFc*Dc, w2h + (size_t)l*FFc*Dc, FFc, Dc);
        cudaEventRecord(evW[l], s3);
    }

    prep_kernel<<<1, Bc>>>(src, pad, dp, mk);
    cudaEventRecord(ePrep, 0);
    embed_kernel<<<HROWS, 256>>>(src, tok_emb, seq_pos, dig_pos, cls_tok, dp, x, xh, 0);
    cudaStreamWaitEvent(s2, ePrep, 0);
    embed_kernel<<<HROWS, 256, 0, s2>>>(src, tok_emb, seq_pos, dig_pos, cls_tok, dp, x, xh, HROWS);

    const int Mh  = HROWS;
    const int MBh = (Mh + 127) / 128;   // 17
    const size_t roff = (size_t)Mh;

    for (int l = 0; l < NLc - 1; l++) {
        const __half* wq_l = wqh + (size_t)l*Dc*3*Dc;
        const __half* wo_l = woh + (size_t)l*Dc*Dc;
        const __half* w1_l = w1h + (size_t)l*Dc*FFc;
        const __half* w2_l = w2h + (size_t)l*FFc*Dc;
        const float*  qb_l = qkv_b + (size_t)l*3*Dc;
        const float*  ob_l = out_b + (size_t)l*Dc;
        const float*  b1_l = l1b + (size_t)l*FFc;
        const float*  b2_l = l2b + (size_t)l*Dc;
        const float*  rel_l = rel + (size_t)l*129*Hc;
        const float*  g1 = ln1g + (size_t)l*Dc, *bb1 = ln1b + (size_t)l*Dc;
        const float*  g2 = ln2g + (size_t)l*Dc, *bb2 = ln2b + (size_t)l*Dc;

        cudaStreamWaitEvent(0,  evW[l], 0);
        cudaStreamWaitEvent(s2, evW[l], 0);

        // half 0 (default stream), grouped
        gemm_h<<<dim3(3*Dc/128, MBh), 256, GEMM_SMEM_H, 0>>>(
            xh, wq_l, qb_l, nullptr, qkvh, Mh, 3*Dc, Dc, 3*Dc, 0, 1);
        attn_h<<<dim3(9, 64), 128, ATT_SMEM_H, 0>>>(qkvh, rel_l, mk, aoh, 0);
        gemm_h<<<dim3(Dc/128, MBh), 256, GEMM_SMEM_H, 0>>>(
            aoh, wo_l, ob_l, x, pr, Mh, Dc, Dc, Dc, 0, 0);
        ln_kernel<<<Mh, 256, 0, 0>>>(pr, x, g1, bb1, xh);
        gemm_h<<<dim3(FFc/128, MBh), 256, GEMM_SMEM_H, 0>>>(
            xh, w1_l, b1_l, nullptr, f1h, Mh, FFc, Dc, FFc, 1, 1);
        gemm_h<<<dim3(Dc/128, MBh), 256, GEMM_SMEM_H, 0>>>(
            f1h, w2_l, b2_l, x, f2, Mh, Dc, FFc, Dc, 0, 0);
        ln_kernel<<<Mh, 256, 0, 0>>>(f2, x, g2, bb2, xh);

        // half 1 (side stream), grouped
        gemm_h<<<dim3(3*Dc/128, MBh), 256, GEMM_SMEM_H, s2>>>(
            xh + roff*Dc, wq_l, qb_l, nullptr, qkvh + roff*3*Dc, Mh, 3*Dc, Dc, 3*Dc, 0, 1);
        attn_h<<<dim3(9, 64), 128, ATT_SMEM_H, s2>>>(qkvh, rel_l, mk, aoh, 64);
        gemm_h<<<dim3(Dc/128, MBh), 256, GEMM_SMEM_H, s2>>>(
            aoh + roff*Dc, wo_l, ob_l, x + roff*Dc, pr + roff*Dc, Mh, Dc, Dc, Dc, 0, 0);
        ln_kernel<<<Mh, 256, 0, s2>>>(pr + roff*Dc, x + roff*Dc, g1, bb1, xh + roff*Dc);
        gemm_h<<<dim3(FFc/128, MBh), 256, GEMM_SMEM_H, s2>>>(
            xh + roff*Dc, w1_l, b1_l, nullptr, f1h + roff*FFc, Mh, FFc, Dc, FFc, 1, 1);
        gemm_h<<<dim3(Dc/128, MBh), 256, GEMM_SMEM_H, s2>>>(
            f1h + roff*FFc, w2_l, b2_l, x + roff*Dc, f2 + roff*Dc, Mh, Dc, FFc, Dc, 0, 0);
        ln_kernel<<<Mh, 256, 0, s2>>>(f2 + roff*Dc, x + roff*Dc, g2, bb2, xh + roff*Dc);
    }

    // ---- layer 5: KV-only qkv for all rows, single-query CLS attention, fp32 tail ----
    {
        const int l = NLc - 1;
        const __half* wq_l = wqh + (size_t)l*Dc*3*Dc;
        const float*  qb_l = qkv_b + (size_t)l*3*Dc;
        const float*  rel_l = rel + (size_t)l*129*Hc;

        cudaStreamWaitEvent(0,  evW[l], 0);
        cudaStreamWaitEvent(s2, evW[l], 0);
        cudaEventRecord(eLn1, s2);   // half-1 residual x ready

        gemm_h<<<dim3(2048/128, MBh), 256, GEMM_SMEM_H, 0>>>(
            xh, wq_l + (size_t)1024*Dc, qb_l + 1024, nullptr,
            qkvh + 1024, Mh, 2048, Dc, 3*Dc, 0, 1);
        gemm_h<<<dim3(2048/128, MBh), 256, GEMM_SMEM_H, s2>>>(
            xh + roff*Dc, wq_l + (size_t)1024*Dc, qb_l + 1024, nullptr,
            qkvh + roff*3*Dc + 1024, Mh, 2048, Dc, 3*Dc, 0, 1);
        cudaEventRecord(eD1, s2);

        cudaStreamWaitEvent(0, eLn1, 0);
        cls_gatherx<<<Bc, 256>>>(x, cxc);
        cls_gemm<<<dim3(Bc, Dc/64), 256>>>(cxc, wq_l, qb_l, cqv, Dc, Dc, 0);

        cudaStreamWaitEvent(0, eD1, 0);
        cls_attn<<<Bc*Hc, 128>>>(qkvh, cqv, rel_l, mk, caf);

        const __half* wo_l = woh + (size_t)l*Dc*Dc;
        const __half* w1_l = w1h + (size_t)l*Dc*FFc;
        const __half* w2_l = w2h + (size_t)l*FFc*Dc;
        cls_gemm<<<dim3(Bc, Dc/64), 256>>>(caf, wo_l, out_b + (size_t)l*Dc, cty, Dc, Dc, 0);
        cls_ln<<<Bc, 256>>>(cxc, cty, ln1g + (size_t)l*Dc, ln1b + (size_t)l*Dc);
        cls_gemm<<<dim3(Bc, FFc/64), 256>>>(cxc, w1_l, l1b + (size_t)l*FFc, cth, FFc, Dc, 1);
        cls_gemm<<<dim3(Bc, Dc/64), 256>>>(cth, w2_l, l2b + (size_t)l*Dc, cty, Dc, FFc, 0);
        cls_ln<<<Bc, 256>>>(cxc, cty, ln2g + (size_t)l*Dc, ln2b + (size_t)l*Dc);
        cls_final<<<Bc, 256>>>(cxc, fng, fnb, clsw, clsb, (float*)d_out);
    }

    cudaEventDestroy(e0);
    cudaEventDestroy(ePrep);
    cudaEventDestroy(eLn1);
    cudaEventDestroy(eD1);
    for (int l = 0; l < NLc; l++) cudaEventDestroy(evW[l]);
    cudaStreamDestroy(s2);
    cudaStreamDestroy(s3);
}

// round 17
// speedup vs baseline: 1.0267x; 1.0267x over previous
#include <cuda_runtime.h>
#include <cuda_fp16.h>
#include <math.h>
#include <stdint.h>

// ---------------- problem constants ----------------
#define Bc   8
#define Lc   512
#define Sc   513
#define Dc   1024
#define Hc   16
#define NLc  6
#define FFc  4096
#define NCc  10
#define BSr  (Bc*Sc)          // 4104 token rows
#define OUTN 80
#define HROWS (4*Sc)          // 2052 rows per batch-half

// ---------------- scratch ----------------
__device__ float  g_x[BSr*Dc];
__device__ float  g_proj[BSr*Dc];
__device__ float  g_ff2[BSr*Dc];
__device__ __half g_xh[BSr*Dc];
__device__ __half g_qkvh[BSr*3*Dc];
__device__ __half g_aoh[BSr*Dc];
__device__ __half g_f1h[BSr*FFc];
__device__ __half g_wqh[(size_t)NLc*Dc*3*Dc];
__device__ __half g_woh[(size_t)NLc*Dc*Dc];
__device__ __half g_w1h[(size_t)NLc*Dc*FFc];
__device__ __half g_w2h[(size_t)NLc*FFc*Dc];
__device__ int           g_dpos[Bc*Lc];
__device__ unsigned char g_mask[Bc*Sc];
// CLS tail scratch
__device__ float g_caf[Bc*Dc];
__device__ float g_cxc[Bc*Dc];
__device__ float g_cty[Bc*Dc];
__device__ float g_cth[Bc*FFc];
__device__ float g_cqv[Bc*Dc];

__device__ __forceinline__ float gelu_f(float v) {
    return 0.5f * v * (1.0f + erff(v * 0.7071067811865476f));
}
__device__ __forceinline__ void cp16(void* dst_smem, const void* src, bool p) {
    unsigned int d = (unsigned int)__cvta_generic_to_shared(dst_smem);
    int sz = p ? 16 : 0;
    asm volatile("cp.async.cg.shared.global [%0], [%1], 16, %2;\n"
                 :: "r"(d), "l"(src), "r"(sz));
}
// polynomial e^x for x <= 0 (fma/alu pipes; MUFU-free)
__device__ __forceinline__ float exp_poly(float x) {
    float t = x * 1.4426950408889634f;
    t = fmaxf(t, -126.0f);
    float n = rintf(t);
    float g = (t - n) * 0.6931471805599453f;
    float p = fmaf(g, 1.0f/120.0f, 1.0f/24.0f);
    p = fmaf(p, g, 1.0f/6.0f);
    p = fmaf(p, g, 0.5f);
    p = fmaf(p, g, 1.0f);
    p = fmaf(p, g, 1.0f);
    int e = (int)n;
    float sc = __int_as_float((unsigned)(e + 127) << 23);
    return p * sc;
}

// ---------------- prep ----------------
__global__ void prep_kernel(const int* __restrict__ src,
                            const unsigned char* __restrict__ pad,
                            int* __restrict__ dpos, unsigned char* __restrict__ mask) {
    int b = threadIdx.x;
    if (b >= Bc) return;
    int c = 0;
    for (int j = Lc - 1; j >= 0; j--) {
        if (src[b*Lc + j] < NCc) { dpos[b*Lc + j] = c; c++; }
        else                     { dpos[b*Lc + j] = -1; c = 0; }
    }
    mask[b*Sc] = 0;
    for (int j = 0; j < Lc; j++) mask[b*Sc + 1 + j] = pad[b*Lc + j];
}

// ---------------- weight transpose + fp16: W[K][N] -> Wh[N][K] (one layer) ----------------
__global__ void transph(const float* __restrict__ W, __half* __restrict__ Wt,
                        int K, int N) {
    __shared__ float t[32][33];
    int n0 = blockIdx.x*32, k0 = blockIdx.y*32;
    for (int i = threadIdx.y; i < 32; i += 8)
        t[i][threadIdx.x] = W[(size_t)(k0 + i)*N + n0 + threadIdx.x];
    __syncthreads();
    for (int i = threadIdx.y; i < 32; i += 8)
        Wt[(size_t)(n0 + i)*K + k0 + threadIdx.x] = __float2half_rn(t[threadIdx.x][i]);
}

// ---------------- embedding (row range [t0, t0+grid), writes x fp32 and xh fp16) ----------------
__global__ void embed_kernel(const int* __restrict__ src,
                             const float* __restrict__ tok_emb,
                             const float* __restrict__ seq_pos,
                             const float* __restrict__ dig_pos,
                             const float* __restrict__ cls_tok,
                             const int* __restrict__ dpos,
                             float* __restrict__ x, __half* __restrict__ xh, int t0) {
    int t = blockIdx.x + t0;
    int b = t / Sc, s = t % Sc;
    int d4 = threadIdx.x;
    float4 v;
    if (s == 0) {
        v = ((const float4*)cls_tok)[d4];
    } else {
        int tok = src[b*Lc + s - 1];
        float4 a = ((const float4*)(tok_emb + (size_t)tok * Dc))[d4];
        float4 p = ((const float4*)(seq_pos + (size_t)(s - 1) * Dc))[d4];
        v.x = a.x + p.x; v.y = a.y + p.y; v.z = a.z + p.z; v.w = a.w + p.w;
        int dp = dpos[b*Lc + s - 1];
        if (dp >= 0) {
            float4 g = ((const float4*)(dig_pos + (size_t)dp * Dc))[d4];
            v.x += g.x; v.y += g.y; v.z += g.z; v.w += g.w;
        }
    }
    ((float4*)(x + (size_t)t * Dc))[d4] = v;
    __half2* xo = (__half2*)(xh + (size_t)t * Dc);
    xo[d4*2]     = __float22half2_rn(make_float2(v.x, v.y));
    xo[d4*2 + 1] = __float22half2_rn(make_float2(v.z, v.w));
}

// ---------------- fp16 tensor-core GEMM, 2-stage cp.async, 2 CTAs/SM ----------------
#define SAh 72
#define AHSZ (128*SAh)
#define STGH (2*AHSZ)
#define GEMM_SMEM_H (2*STGH*2)

__global__ __launch_bounds__(256, 2) void gemm_h(const __half* __restrict__ A,
                                                 const __half* __restrict__ W,
                                                 const float* __restrict__ bias,
                                                 void* __restrict__ Cv,
                                                 int M, int N, int K, int ldc,
                                                 int act, int outh) {
    extern __shared__ __half hsm[];
    int bm = blockIdx.y * 128, bn = blockIdx.x * 128;
    int tid = threadIdx.x;
    int wid = tid >> 5, lane = tid & 31;
    int wm = (wid >> 1) * 32;
    int wn = (wid & 1) * 64;
    int lr = lane >> 2, lc = lane & 3;

    float c[2][8][4];
    #pragma unroll
    for (int mt = 0; mt < 2; mt++)
        #pragma unroll
        for (int nt = 0; nt < 8; nt++)
            #pragma unroll
            for (int i = 0; i < 4; i++) c[mt][nt][i] = 0.f;

    auto load_stage = [&](int s, int k0) {
        __half* Ah = hsm + s * STGH;
        __half* Bh = Ah + AHSZ;
        #pragma unroll
        for (int i = 0; i < 4; i++) {
            int idx = i*256 + tid;
            int r = idx >> 3, cc = idx & 7;
            int gm = bm + r;
            const __half* srcp = A + (size_t)(gm < M ? gm : M-1)*K + k0 + cc*8;
            cp16(&Ah[r*SAh + cc*8], srcp, gm < M);
        }
        #pragma unroll
        for (int i = 0; i < 4; i++) {
            int idx = i*256 + tid;
            int r = idx >> 3, cc = idx & 7;
            cp16(&Bh[r*SAh + cc*8], W + (size_t)(bn + r)*K + k0 + cc*8, true);
        }
    };

    int kT = K / 64;
    load_stage(0, 0);   asm volatile("cp.async.commit_group;\n" ::: "memory");
    load_stage(1, 64);  asm volatile("cp.async.commit_group;\n" ::: "memory");

    for (int t = 0; t < kT; t++) {
        asm volatile("cp.async.wait_group 1;\n" ::: "memory");
        __syncthreads();
        int s = t & 1;
        const __half* Ah = hsm + s * STGH;
        const __half* Bh = Ah + AHSZ;

        #pragma unroll
        for (int kk = 0; kk < 4; kk++) {
            unsigned int af[2][4];
            #pragma unroll
            for (int mt = 0; mt < 2; mt++) {
                int base = (wm + mt*16 + lr)*SAh + kk*16 + 2*lc;
                af[mt][0] = *(const unsigned int*)&Ah[base];
                af[mt][1] = *(const unsigned int*)&Ah[base + 8*SAh];
                af[mt][2] = *(const unsigned int*)&Ah[base + 8];
                af[mt][3] = *(const unsigned int*)&Ah[base + 8*SAh + 8];
            }
            #pragma unroll
            for (int nt = 0; nt < 8; nt++) {
                int bbase = (wn + nt*8 + lr)*SAh + kk*16 + 2*lc;
                unsigned int b0 = *(const unsigned int*)&Bh[bbase];
                unsigned int b1 = *(const unsigned int*)&Bh[bbase + 8];
                #pragma unroll
                for (int mt = 0; mt < 2; mt++) {
                    asm volatile(
                        "mma.sync.aligned.m16n8k16.row.col.f32.f16.f16.f32 "
                        "{%0,%1,%2,%3}, {%4,%5,%6,%7}, {%8,%9}, {%0,%1,%2,%3};"
                        : "+f"(c[mt][nt][0]), "+f"(c[mt][nt][1]),
                          "+f"(c[mt][nt][2]), "+f"(c[mt][nt][3])
                        : "r"(af[mt][0]), "r"(af[mt][1]), "r"(af[mt][2]), "r"(af[mt][3]),
                          "r"(b0), "r"(b1));
                }
            }
        }
        __syncthreads();
        if (t + 2 < kT) load_stage(s, (t + 2) * 64);
        asm volatile("cp.async.commit_group;\n" ::: "memory");
    }

    float*  Cf = (float*)Cv;
    __half* Ch = (__half*)Cv;
    #pragma unroll
    for (int mt = 0; mt < 2; mt++) {
        #pragma unroll
        for (int nt = 0; nt < 8; nt++) {
            int col = bn + wn + nt*8 + lc*2;
            float b0v = bias[col], b1v = bias[col + 1];
            int row0 = bm + wm + mt*16 + lr;
            if (row0 < M) {
                float v0 = c[mt][nt][0] + b0v;
                float v1 = c[mt][nt][1] + b1v;
                if (act) { v0 = gelu_f(v0); v1 = gelu_f(v1); }
                if (outh) *(__half2*)(Ch + (size_t)row0*ldc + col) = __float22half2_rn(make_float2(v0, v1));
                else      *(float2*)(Cf + (size_t)row0*ldc + col) = make_float2(v0, v1);
            }
            int row1 = row0 + 8;
            if (row1 < M) {
                float v2 = c[mt][nt][2] + b0v;
                float v3 = c[mt][nt][3] + b1v;
                if (act) { v2 = gelu_f(v2); v3 = gelu_f(v3); }
                if (outh) *(__half2*)(Ch + (size_t)row1*ldc + col) = __float22half2_rn(make_float2(v2, v3));
                else      *(float2*)(Cf + (size_t)row1*ldc + col) = make_float2(v2, v3);
            }
        }
    }
}

// ---------------- fp16 flash attention: double-buffered cp.async K/V ----------------
#define AS2 72
#define KVT (64*AS2)
#define ATT_SMEM_H (5*KVT*2 + 132*4 + 640)

__global__ __launch_bounds__(128) void attn_h(const __half* __restrict__ qkv,
                                              const float* __restrict__ rel_l,
                                              const unsigned char* __restrict__ mask,
                                              __half* __restrict__ out, int bh0) {
    extern __shared__ __half ash[];
    __half* Qh = ash;
    __half* Kb = Qh + KVT;
    __half* Vb = Kb + 2*KVT;
    float* rel_s = (float*)(Vb + 2*KVT);
    unsigned char* msk = (unsigned char*)(rel_s + 132);

    int bh = blockIdx.y + bh0;
    int b = bh >> 4, h = bh & 15;
    int q0 = blockIdx.x * 64;
    int tid = threadIdx.x;
    int wq = tid >> 5;
    int lane = tid & 31;
    int lr = lane >> 2, lc = lane & 3;
    int r0 = wq*16 + lr;

    for (int i = tid; i < 129; i += 128) rel_s[i] = rel_l[i*Hc + h];
    const unsigned char* mrow = mask + b*Sc;
    for (int i = tid; i < Sc; i += 128) msk[i] = mrow[i];
    for (int i = tid; i < 64*8; i += 128) {
        int q = i >> 3, cc = i & 7;
        int gq = q0 + q;
        uint4 v = make_uint4(0u,0u,0u,0u);
        if (gq < Sc) v = *(const uint4*)(qkv + (size_t)(b*Sc + gq)*3072 + h*64 + cc*8);
        *(uint4*)&Qh[q*AS2 + cc*8] = v;
    }

    auto load_kv = [&](int s, int kt) {
        int k0 = kt * 64;
        __half* Kh = Kb + s*KVT;
        __half* Vh = Vb + s*KVT;
        #pragma unroll
        for (int i2 = 0; i2 < 4; i2++) {
            int i = i2*128 + tid;
            int tok = i >> 3, cc = i & 7;
            int k = k0 + tok;
            int kc = k < Sc ? k : Sc - 1;
            const __half* base = qkv + (size_t)(b*Sc + kc)*3072 + h*64 + cc*8;
            cp16(&Kh[tok*AS2 + cc*8], base + 1024, k < Sc);
            cp16(&Vh[tok*AS2 + cc*8], base + 2048, k < Sc);
        }
    };

    load_kv(0, 0);
    asm volatile("cp.async.commit_group;" ::: "memory");
    __syncthreads();

    unsigned int qf[4][4];
    #pragma unroll
    for (int kk = 0; kk < 4; kk++) {
        int base = r0*AS2 + kk*16 + 2*lc;
        qf[kk][0] = *(const unsigned int*)&Qh[base];
        qf[kk][1] = *(const unsigned int*)&Qh[base + 8*AS2];
        qf[kk][2] = *(const unsigned int*)&Qh[base + 8];
        qf[kk][3] = *(const unsigned int*)&Qh[base + 8*AS2 + 8];
    }

    uint32_t vb0 = (uint32_t)__cvta_generic_to_shared(Vb);
    int vrow = lane & 15;
    int vcol = (lane >> 4) * 8;

    float m0 = -1e30f, m1 = -1e30f, l0 = 0.f, l1 = 0.f;
    float o[8][4];
    #pragma unroll
    for (int nt = 0; nt < 8; nt++)
        #pragma unroll
        for (int i = 0; i < 4; i++) o[nt][i] = 0.f;

    for (int kt = 0; kt < 9; kt++) {
        if (kt + 1 < 9) load_kv((kt + 1) & 1, kt + 1);
        asm volatile("cp.async.commit_group;" ::: "memory");
        if (kt + 1 < 9) asm volatile("cp.async.wait_group 1;" ::: "memory");
        else            asm volatile("cp.async.wait_group 0;" ::: "memory");
        __syncthreads();

        int sbi = kt & 1;
        const __half* Kh = Kb + sbi*KVT;
        uint32_t vbase = vb0 + (uint32_t)(sbi*KVT*2);
        int k0 = kt * 64;

        float s[8][4];
        #pragma unroll
        for (int nt = 0; nt < 8; nt++)
            #pragma unroll
            for (int i = 0; i < 4; i++) s[nt][i] = 0.f;
        #pragma unroll
        for (int kk = 0; kk < 4; kk++) {
            #pragma unroll
            for (int nt = 0; nt < 8; nt++) {
                int bbase = (nt*8 + lr)*AS2 + kk*16 + 2*lc;
                unsigned int b0 = *(const unsigned int*)&Kh[bbase];
                unsigned int b1 = *(const unsigned int*)&Kh[bbase + 8];
                asm volatile(
                    "mma.sync.aligned.m16n8k16.row.col.f32.f16.f16.f32 "
                    "{%0,%1,%2,%3}, {%4,%5,%6,%7}, {%8,%9}, {%0,%1,%2,%3};"
                    : "+f"(s[nt][0]), "+f"(s[nt][1]), "+f"(s[nt][2]), "+f"(s[nt][3])
                    : "r"(qf[kk][0]), "r"(qf[kk][1]), "r"(qf[kk][2]), "r"(qf[kk][3]),
                      "r"(b0), "r"(b1));
            }
        }

        int q_r0 = q0 + r0, q_r1 = q_r0 + 8;
        #pragma unroll
        for (int nt = 0; nt < 8; nt++) {
            #pragma unroll
            for (int j = 0; j < 2; j++) {
                int k = k0 + nt*8 + 2*lc + j;
                bool ok = (k < Sc) && !msk[k < Sc ? k : 0];
                int rr0 = k - q_r0; rr0 = rr0 < -64 ? -64 : (rr0 > 64 ? 64 : rr0);
                int rr1 = k - q_r1; rr1 = rr1 < -64 ? -64 : (rr1 > 64 ? 64 : rr1);
                s[nt][j]   = ok ? fmaf(s[nt][j],   0.125f, rel_s[rr0 + 64]) : -1e30f;
                s[nt][2+j] = ok ? fmaf(s[nt][2+j], 0.125f, rel_s[rr1 + 64]) : -1e30f;
            }
        }

        float mx0 = -1e30f, mx1 = -1e30f;
        #pragma unroll
        for (int nt = 0; nt < 8; nt++) {
            mx0 = fmaxf(mx0, fmaxf(s[nt][0], s[nt][1]));
            mx1 = fmaxf(mx1, fmaxf(s[nt][2], s[nt][3]));
        }
        mx0 = fmaxf(mx0, __shfl_xor_sync(0xffffffffu, mx0, 1));
        mx0 = fmaxf(mx0, __shfl_xor_sync(0xffffffffu, mx0, 2));
        mx1 = fmaxf(mx1, __shfl_xor_sync(0xffffffffu, mx1, 1));
        mx1 = fmaxf(mx1, __shfl_xor_sync(0xffffffffu, mx1, 2));

        float nm0 = fmaxf(m0, mx0), nm1 = fmaxf(m1, mx1);
        float sc0 = __expf(m0 - nm0), sc1 = __expf(m1 - nm1);

        float sum0 = 0.f, sum1 = 0.f;
        #pragma unroll
        for (int nt = 0; nt < 8; nt++) {
            if (nt & 1) {
                s[nt][0] = exp_poly(s[nt][0] - nm0);
                s[nt][1] = exp_poly(s[nt][1] - nm0);
                s[nt][2] = exp_poly(s[nt][2] - nm1);
                s[nt][3] = exp_poly(s[nt][3] - nm1);
            } else {
                s[nt][0] = __expf(s[nt][0] - nm0);
                s[nt][1] = __expf(s[nt][1] - nm0);
                s[nt][2] = __expf(s[nt][2] - nm1);
                s[nt][3] = __expf(s[nt][3] - nm1);
            }
            sum0 += s[nt][0] + s[nt][1];
            sum1 += s[nt][2] + s[nt][3];
        }
        sum0 += __shfl_xor_sync(0xffffffffu, sum0, 1);
        sum0 += __shfl_xor_sync(0xffffffffu, sum0, 2);
        sum1 += __shfl_xor_sync(0xffffffffu, sum1, 1);
        sum1 += __shfl_xor_sync(0xffffffffu, sum1, 2);

        m0 = nm0; m1 = nm1;
        l0 = l0*sc0 + sum0;
        l1 = l1*sc1 + sum1;
        #pragma unroll
        for (int nt = 0; nt < 8; nt++) {
            o[nt][0] *= sc0; o[nt][1] *= sc0;
            o[nt][2] *= sc1; o[nt][3] *= sc1;
        }

        #pragma unroll
        for (int kk = 0; kk < 4; kk++) {
            __half2 a0h = __float22half2_rn(make_float2(s[2*kk][0],   s[2*kk][1]));
            __half2 a1h = __float22half2_rn(make_float2(s[2*kk][2],   s[2*kk][3]));
            __half2 a2h = __float22half2_rn(make_float2(s[2*kk+1][0], s[2*kk+1][1]));
            __half2 a3h = __float22half2_rn(make_float2(s[2*kk+1][2], s[2*kk+1][3]));
            unsigned int a0 = *(unsigned int*)&a0h;
            unsigned int a1 = *(unsigned int*)&a1h;
            unsigned int a2 = *(unsigned int*)&a2h;
            unsigned int a3 = *(unsigned int*)&a3h;
            #pragma unroll
            for (int np = 0; np < 4; np++) {
                unsigned int r0v, r1v, r2v, r3v;
                uint32_t addr = vbase + 2u*((kk*16 + vrow)*AS2 + np*16 + vcol);
                asm volatile(
                    "ldmatrix.sync.aligned.m8n8.x4.trans.shared.b16 {%0,%1,%2,%3}, [%4];"
                    : "=r"(r0v), "=r"(r1v), "=r"(r2v), "=r"(r3v) : "r"(addr));
                asm volatile(
                    "mma.sync.aligned.m16n8k16.row.col.f32.f16.f16.f32 "
                    "{%0,%1,%2,%3}, {%4,%5,%6,%7}, {%8,%9}, {%0,%1,%2,%3};"
                    : "+f"(o[2*np][0]), "+f"(o[2*np][1]), "+f"(o[2*np][2]), "+f"(o[2*np][3])
                    : "r"(a0), "r"(a1), "r"(a2), "r"(a3), "r"(r0v), "r"(r1v));
                asm volatile(
                    "mma.sync.aligned.m16n8k16.row.col.f32.f16.f16.f32 "
                    "{%0,%1,%2,%3}, {%4,%5,%6,%7}, {%8,%9}, {%0,%1,%2,%3};"
                    : "+f"(o[2*np+1][0]), "+f"(o[2*np+1][1]), "+f"(o[2*np+1][2]), "+f"(o[2*np+1][3])
                    : "r"(a0), "r"(a1), "r"(a2), "r"(a3), "r"(r2v), "r"(r3v));
            }
        }
        __syncthreads();
    }

    float inv0 = 1.0f / l0, inv1 = 1.0f / l1;
    int gq0 = q0 + r0, gq1 = gq0 + 8;
    #pragma unroll
    for (int nt = 0; nt < 8; nt++) {
        int col = h*64 + nt*8 + 2*lc;
        if (gq0 < Sc)
            *(__half2*)&out[(size_t)(b*Sc + gq0)*Dc + col] =
                __float22half2_rn(make_float2(o[nt][0]*inv0, o[nt][1]*inv0));
        if (gq1 < Sc)
            *(__half2*)&out[(size_t)(b*Sc + gq1)*Dc + col] =
                __float22half2_rn(make_float2(o[nt][2]*inv1, o[nt][3]*inv1));
    }
}

// ---------------- residual add + layernorm ----------------
__global__ void add_ln_kernel(float* __restrict__ x, const float* __restrict__ r,
                              const float* __restrict__ g, const float* __restrict__ bta,
                              __half* __restrict__ xh) {
    int row = blockIdx.x;
    int tid = threadIdx.x;
    __shared__ float red[16];
    float4 xv = ((float4*)(x + (size_t)row*Dc))[tid];
    float4 rv = ((const float4*)(r + (size_t)row*Dc))[tid];
    xv.x += rv.x; xv.y += rv.y; xv.z += rv.z; xv.w += rv.w;
    float s  = xv.x + xv.y + xv.z + xv.w;
    float s2 = xv.x*xv.x + xv.y*xv.y + xv.z*xv.z + xv.w*xv.w;
    #pragma unroll
    for (int o = 16; o; o >>= 1) {
        s  += __shfl_xor_sync(0xffffffffu, s,  o);
        s2 += __shfl_xor_sync(0xffffffffu, s2, o);
    }
    int w = tid >> 5;
    if ((tid & 31) == 0) { red[w] = s; red[8 + w] = s2; }
    __syncthreads();
    float ts = 0.f, ts2 = 0.f;
    #pragma unroll
    for (int i = 0; i < 8; i++) { ts += red[i]; ts2 += red[8 + i]; }
    float mean = ts * (1.0f/Dc);
    float rstd = rsqrtf(ts2 * (1.0f/Dc) - mean*mean + 1e-5f);
    float4 gv = ((const float4*)g)[tid];
    float4 bv = ((const float4*)bta)[tid];
    float4 o;
    o.x = (xv.x - mean)*rstd*gv.x + bv.x;
    o.y = (xv.y - mean)*rstd*gv.y + bv.y;
    o.z = (xv.z - mean)*rstd*gv.z + bv.z;
    o.w = (xv.w - mean)*rstd*gv.w + bv.w;
    ((float4*)(x + (size_t)row*Dc))[tid] = o;
    __half2* xo = (__half2*)(xh + (size_t)row*Dc);
    xo[tid*2]     = __float22half2_rn(make_float2(o.x, o.y));
    xo[tid*2 + 1] = __float22half2_rn(make_float2(o.z, o.w));
}

// ---------------- CLS tail kernels ----------------
__global__ void cls_gatherx(const float* __restrict__ x, float* __restrict__ xc) {
    int b = blockIdx.x, tid = threadIdx.x;
    for (int i = tid; i < Dc; i += 256)
        xc[b*Dc + i] = x[(size_t)(b*Sc)*Dc + i];
}

__global__ void cls_gemm(const float* __restrict__ A, const __half* __restrict__ W,
                         const float* __restrict__ bias, float* __restrict__ Y,
                         int N, int K, int act) {
    __shared__ float As[FFc];
    int b = blockIdx.x;
    int n0 = blockIdx.y * 64;
    int tid = threadIdx.x, wid = tid >> 5, lane = tid & 31;
    for (int i = tid; i < K; i += 256) As[i] = A[b*K + i];
    __syncthreads();
    #pragma unroll
    for (int j = 0; j < 8; j++) {
        int n = n0 + wid*8 + j;
        const __half2* wr = (const __half2*)(W + (size_t)n*K);
        float acc = 0.f;
        for (int k2 = lane; k2 < K/2; k2 += 32) {
            float2 wv = __half22float2(wr[k2]);
            acc = fmaf(As[2*k2], wv.x, acc);
            acc = fmaf(As[2*k2+1], wv.y, acc);
        }
        #pragma unroll
        for (int o = 16; o; o >>= 1) acc += __shfl_xor_sync(0xffffffffu, acc, o);
        if (lane == 0) {
            float v = acc + bias[n];
            if (act) v = gelu_f(v);
            Y[b*N + n] = v;
        }
    }
}

// single-query (CLS) attention: grid 128 = (b,h), block 128. fp32 math.
__global__ void cls_attn(const __half* __restrict__ qkv,
                         const float* __restrict__ q8,
                         const float* __restrict__ rel_l,
                         const unsigned char* __restrict__ mask,
                         float* __restrict__ caf) {
    int bh = blockIdx.x;
    int b = bh >> 4, h = bh & 15;
    int tid = threadIdx.x;
    __shared__ float p[520];
    __shared__ float qs[64];
    __shared__ float red[4];
    __shared__ float ob[64];
    if (tid < 64) { qs[tid] = q8[b*Dc + h*64 + tid]; ob[tid] = 0.f; }
    __syncthreads();
    float lm = -1e30f;
    for (int k = tid; k < Sc; k += 128) {
        const __half* kr = qkv + (size_t)(b*Sc + k)*3072 + 1024 + h*64;
        float acc = 0.f;
        #pragma unroll 16
        for (int d = 0; d < 64; d++) acc = fmaf(qs[d], __half2float(kr[d]), acc);
        int rr = k > 64 ? 64 : k;
        float v = -1e30f;
        if (!mask[b*Sc + k]) v = acc*0.125f + rel_l[(rr + 64)*Hc + h];
        p[k] = v;
        lm = fmaxf(lm, v);
    }
    #pragma unroll
    for (int o = 16; o; o >>= 1) lm = fmaxf(lm, __shfl_xor_sync(0xffffffffu, lm, o));
    if ((tid & 31) == 0) red[tid >> 5] = lm;
    __syncthreads();
    float m = fmaxf(fmaxf(red[0], red[1]), fmaxf(red[2], red[3]));
    __syncthreads();
    float ls = 0.f;
    for (int k = tid; k < Sc; k += 128) {
        float e = __expf(p[k] - m);
        p[k] = e;
        ls += e;
    }
    #pragma unroll
    for (int o = 16; o; o >>= 1) ls += __shfl_xor_sync(0xffffffffu, ls, o);
    if ((tid & 31) == 0) red[tid >> 5] = ls;
    __syncthreads();
    float inv = 1.0f / (red[0] + red[1] + red[2] + red[3]);
    int d = tid & 63, hk = tid >> 6;
    float acc = 0.f;
    for (int k = hk; k < Sc; k += 2)
        acc = fmaf(p[k], __half2float(qkv[(size_t)(b*Sc + k)*3072 + 2048 + h*64 + d]), acc);
    atomicAdd(&ob[d], acc);
    __syncthreads();
    if (tid < 64) caf[b*Dc + h*64 + tid] = ob[tid] * inv;
}

// xc = LN(xc + y)
__global__ void cls_ln(float* __restrict__ xc, const float* __restrict__ y,
                       const float* __restrict__ g, const float* __restrict__ bta) {
    int b = blockIdx.x, tid = threadIdx.x;
    __shared__ float red[16];
    float4 xv = ((float4*)(xc + b*Dc))[tid];
    float4 yv = ((const float4*)(y + b*Dc))[tid];
    xv.x += yv.x; xv.y += yv.y; xv.z += yv.z; xv.w += yv.w;
    float s  = xv.x + xv.y + xv.z + xv.w;
    float s2 = xv.x*xv.x + xv.y*xv.y + xv.z*xv.z + xv.w*xv.w;
    #pragma unroll
    for (int o = 16; o; o >>= 1) {
        s  += __shfl_xor_sync(0xffffffffu, s,  o);
        s2 += __shfl_xor_sync(0xffffffffu, s2, o);
    }
    int w = tid >> 5;
    if ((tid & 31) == 0) { red[w] = s; red[8 + w] = s2; }
    __syncthreads();
    float ts = 0.f, ts2 = 0.f;
    #pragma unroll
    for (int i = 0; i < 8; i++) { ts += red[i]; ts2 += red[8 + i]; }
    float mean = ts * (1.0f/Dc);
    float rstd = rsqrtf(ts2 * (1.0f/Dc) - mean*mean + 1e-5f);
    float4 gv = ((const float4*)g)[tid];
    float4 bv = ((const float4*)bta)[tid];
    float4 o;
    o.x = (xv.x - mean)*rstd*gv.x + bv.x;
    o.y = (xv.y - mean)*rstd*gv.y + bv.y;
    o.z = (xv.z - mean)*rstd*gv.z + bv.z;
    o.w = (xv.w - mean)*rstd*gv.w + bv.w;
    ((float4*)(xc + b*Dc))[tid] = o;
}

// final LN + classifier
__global__ void cls_final(const float* __restrict__ xc,
                          const float* __restrict__ g, const float* __restrict__ bta,
                          const float* __restrict__ w, const float* __restrict__ cb,
                          float* __restrict__ out) {
    int bb = blockIdx.x;
    const float* row = xc + bb * Dc;
    __shared__ float xn[Dc];
    __shared__ float red[16];
    int tid = threadIdx.x;
    float4 v = ((const float4*)row)[tid];
    float s  = v.x + v.y + v.z + v.w;
    float s2 = v.x*v.x + v.y*v.y + v.z*v.z + v.w*v.w;
    #pragma unroll
    for (int o = 16; o; o >>= 1) {
        s  += __shfl_xor_sync(0xffffffffu, s,  o);
        s2 += __shfl_xor_sync(0xffffffffu, s2, o);
    }
    int wr = tid >> 5;
    if ((tid & 31) == 0) { red[wr] = s; red[8 + wr] = s2; }
    __syncthreads();
    float ts = 0.f, ts2 = 0.f;
    #pragma unroll
    for (int i = 0; i < 8; i++) { ts += red[i]; ts2 += red[8 + i]; }
    float mean = ts * (1.0f/Dc);
    float rstd = rsqrtf(ts2 * (1.0f/Dc) - mean*mean + 1e-5f);
    float4 gv = ((const float4*)g)[tid];
    float4 bv = ((const float4*)bta)[tid];
    xn[tid*4 + 0] = (v.x - mean)*rstd*gv.x + bv.x;
    xn[tid*4 + 1] = (v.y - mean)*rstd*gv.y + bv.y;
    xn[tid*4 + 2] = (v.z - mean)*rstd*gv.z + bv.z;
    xn[tid*4 + 3] = (v.w - mean)*rstd*gv.w + bv.w;
    __syncthreads();
    int wid = tid >> 5, lane = tid & 31;
    for (int n = wid; n < OUTN; n += 8) {
        float a = 0.f;
        for (int k = lane; k < Dc; k += 32) a = fmaf(xn[k], w[(size_t)k*OUTN + n], a);
        #pragma unroll
        for (int o = 16; o; o >>= 1) a += __shfl_xor_sync(0xffffffffu, a, o);
        if (lane == 0) out[bb*OUTN + n] = a + cb[n];
    }
}

// ---------------- launch ----------------
extern "C" void kernel_launch(void* const* d_in, const int* in_sizes, int n_in,
                              void* d_out, int out_size) {
    const int*           src     = (const int*)d_in[0];
    const unsigned char* pad     = (const unsigned char*)d_in[1];
    const float* tok_emb = (const float*)d_in[2];
    const float* seq_pos = (const float*)d_in[3];
    const float* dig_pos = (const float*)d_in[4];
    const float* cls_tok = (const float*)d_in[5];
    const float* qkv_w   = (const float*)d_in[6];
    const float* qkv_b   = (const float*)d_in[7];
    const float* out_w   = (const float*)d_in[8];
    const float* out_b   = (const float*)d_in[9];
    const float* rel     = (const float*)d_in[10];
    const float* ln1g    = (const float*)d_in[11];
    const float* ln1b    = (const float*)d_in[12];
    const float* l1w     = (const float*)d_in[13];
    const float* l1b     = (const float*)d_in[14];
    const float* l2w     = (const float*)d_in[15];
    const float* l2b     = (const float*)d_in[16];
    const float* ln2g    = (const float*)d_in[17];
    const float* ln2b    = (const float*)d_in[18];
    const float* fng     = (const float*)d_in[19];
    const float* fnb     = (const float*)d_in[20];
    const float* clsw    = (const float*)d_in[21];
    const float* clsb    = (const float*)d_in[22];

    float *x, *pr, *f2, *caf, *cxc, *cty, *cth, *cqv;
    __half *xh, *qkvh, *aoh, *f1h, *wqh, *woh, *w1h, *w2h;
    int* dp; unsigned char* mk;
    cudaGetSymbolAddress((void**)&x,   g_x);
    cudaGetSymbolAddress((void**)&pr,  g_proj);
    cudaGetSymbolAddress((void**)&f2,  g_ff2);
    cudaGetSymbolAddress((void**)&xh,  g_xh);
    cudaGetSymbolAddress((void**)&qkvh,g_qkvh);
    cudaGetSymbolAddress((void**)&aoh, g_aoh);
    cudaGetSymbolAddress((void**)&f1h, g_f1h);
    cudaGetSymbolAddress((void**)&wqh, g_wqh);
    cudaGetSymbolAddress((void**)&woh, g_woh);
    cudaGetSymbolAddress((void**)&w1h, g_w1h);
    cudaGetSymbolAddress((void**)&w2h, g_w2h);
    cudaGetSymbolAddress((void**)&dp,  g_dpos);
    cudaGetSymbolAddress((void**)&mk,  g_mask);
    cudaGetSymbolAddress((void**)&caf, g_caf);
    cudaGetSymbolAddress((void**)&cxc, g_cxc);
    cudaGetSymbolAddress((void**)&cty, g_cty);
    cudaGetSymbolAddress((void**)&cth, g_cth);
    cudaGetSymbolAddress((void**)&cqv, g_cqv);

    cudaFuncSetAttribute(gemm_h, cudaFuncAttributeMaxDynamicSharedMemorySize, GEMM_SMEM_H);
    cudaFuncSetAttribute(attn_h, cudaFuncAttributeMaxDynamicSharedMemorySize, ATT_SMEM_H);

    cudaStream_t s2, s3;
    cudaStreamCreateWithFlags(&s2, cudaStreamNonBlocking);
    cudaStreamCreateWithFlags(&s3, cudaStreamNonBlocking);
    cudaEvent_t e0, ePrep, eLn1, eD1;
    cudaEvent_t evW[NLc];
    cudaEventCreateWithFlags(&e0,    cudaEventDisableTiming);
    cudaEventCreateWithFlags(&ePrep, cudaEventDisableTiming);
    cudaEventCreateWithFlags(&eLn1,  cudaEventDisableTiming);
    cudaEventCreateWithFlags(&eD1,   cudaEventDisableTiming);
    for (int l = 0; l < NLc; l++) cudaEventCreateWithFlags(&evW[l], cudaEventDisableTiming);

    // fork: s3 does per-layer weight transposes; s2 does half-1 compute
    cudaEventRecord(e0, 0);
    cudaStreamWaitEvent(s3, e0, 0);
    cudaStreamWaitEvent(s2, e0, 0);
    for (int l = 0; l < NLc; l++) {
        transph<<<dim3(3*Dc/32, Dc/32), dim3(32,8), 0, s3>>>(
            qkv_w + (size_t)l*Dc*3*Dc, wqh + (size_t)l*Dc*3*Dc, Dc, 3*Dc);
        transph<<<dim3(Dc/32, Dc/32), dim3(32,8), 0, s3>>>(
            out_w + (size_t)l*Dc*Dc, woh + (size_t)l*Dc*Dc, Dc, Dc);
        transph<<<dim3(FFc/32, Dc/32), dim3(32,8), 0, s3>>>(
            l1w + (size_t)l*Dc*FFc, w1h + (size_t)l*Dc*FFc, Dc, FFc);
        transph<<<dim3(Dc/32, FFc/32), dim3(32,8), 0, s3>>>(
            l2w + (size_t)l*FFc*Dc, w2h + (size_t)l*FFc*Dc, FFc, Dc);
        cudaEventRecord(evW[l], s3);
    }

    prep_kernel<<<1, Bc>>>(src, pad, dp, mk);
    cudaEventRecord(ePrep, 0);
    embed_kernel<<<HROWS, 256>>>(src, tok_emb, seq_pos, dig_pos, cls_tok, dp, x, xh, 0);
    cudaStreamWaitEvent(s2, ePrep, 0);
    embed_kernel<<<HROWS, 256, 0, s2>>>(src, tok_emb, seq_pos, dig_pos, cls_tok, dp, x, xh, HROWS);

    const int Mh  = HROWS;
    const int MBh = (Mh + 127) / 128;   // 17
    const size_t roff = (size_t)Mh;

    for (int l = 0; l < NLc - 1; l++) {
        const __half* wq_l = wqh + (size_t)l*Dc*3*Dc;
        const __half* wo_l = woh + (size_t)l*Dc*Dc;
        const __half* w1_l = w1h + (size_t)l*Dc*FFc;
        const __half* w2_l = w2h + (size_t)l*FFc*Dc;
        const float*  qb_l = qkv_b + (size_t)l*3*Dc;
        const float*  ob_l = out_b + (size_t)l*Dc;
        const float*  b1_l = l1b + (size_t)l*FFc;
        const float*  b2_l = l2b + (size_t)l*Dc;
        const float*  rel_l = rel + (size_t)l*129*Hc;

        cudaStreamWaitEvent(0,  evW[l], 0);
        cudaStreamWaitEvent(s2, evW[l], 0);

        gemm_h<<<dim3(3*Dc/128, MBh), 256, GEMM_SMEM_H, 0>>>(
            xh, wq_l, qb_l, qkvh, Mh, 3*Dc, Dc, 3*Dc, 0, 1);
        attn_h<<<dim3(9, 64), 128, ATT_SMEM_H, 0>>>(qkvh, rel_l, mk, aoh, 0);
        gemm_h<<<dim3(Dc/128, MBh), 256, GEMM_SMEM_H, 0>>>(
            aoh, wo_l, ob_l, pr, Mh, Dc, Dc, Dc, 0, 0);
        add_ln_kernel<<<Mh, 256, 0, 0>>>(x, pr, ln1g + (size_t)l*Dc, ln1b + (size_t)l*Dc, xh);
        gemm_h<<<dim3(FFc/128, MBh), 256, GEMM_SMEM_H, 0>>>(
            xh, w1_l, b1_l, f1h, Mh, FFc, Dc, FFc, 1, 1);
        gemm_h<<<dim3(Dc/128, MBh), 256, GEMM_SMEM_H, 0>>>(
            f1h, w2_l, b2_l, f2, Mh, Dc, FFc, Dc, 0, 0);
        add_ln_kernel<<<Mh, 256, 0, 0>>>(x, f2, ln2g + (size_t)l*Dc, ln2b + (size_t)l*Dc, xh);

        gemm_h<<<dim3(3*Dc/128, MBh), 256, GEMM_SMEM_H, s2>>>(
            xh + roff*Dc, wq_l, qb_l, qkvh + roff*3*Dc, Mh, 3*Dc, Dc, 3*Dc, 0, 1);
        attn_h<<<dim3(9, 64), 128, ATT_SMEM_H, s2>>>(qkvh, rel_l, mk, aoh, 64);
        gemm_h<<<dim3(Dc/128, MBh), 256, GEMM_SMEM_H, s2>>>(
            aoh + roff*Dc, wo_l, ob_l, pr + roff*Dc, Mh, Dc, Dc, Dc, 0, 0);
        add_ln_kernel<<<Mh, 256, 0, s2>>>(x + roff*Dc, pr + roff*Dc,
                                          ln1g + (size_t)l*Dc, ln1b + (size_t)l*Dc, xh + roff*Dc);
        gemm_h<<<dim3(FFc/128, MBh), 256, GEMM_SMEM_H, s2>>>(
            xh + roff*Dc, w1_l, b1_l, f1h + roff*FFc, Mh, FFc, Dc, FFc, 1, 1);
        gemm_h<<<dim3(Dc/128, MBh), 256, GEMM_SMEM_H, s2>>>(
            f1h + roff*FFc, w2_l, b2_l, f2 + roff*Dc, Mh, Dc, FFc, Dc, 0, 0);
        add_ln_kernel<<<Mh, 256, 0, s2>>>(x + roff*Dc, f2 + roff*Dc,
                                          ln2g + (size_t)l*Dc, ln2b + (size_t)l*Dc, xh + roff*Dc);
    }

    // ---- layer 5: KV-only qkv for all rows, single-query CLS attention, fp32 tail ----
    {
        const int l = NLc - 1;
        const __half* wq_l = wqh + (size_t)l*Dc*3*Dc;
        const float*  qb_l = qkv_b + (size_t)l*3*Dc;
        const float*  rel_l = rel + (size_t)l*129*Hc;

        cudaStreamWaitEvent(0,  evW[l], 0);
        cudaStreamWaitEvent(s2, evW[l], 0);
        cudaEventRecord(eLn1, s2);   // half-1 residual x ready

        gemm_h<<<dim3(2048/128, MBh), 256, GEMM_SMEM_H, 0>>>(
            xh, wq_l + (size_t)1024*Dc, qb_l + 1024,
            qkvh + 1024, Mh, 2048, Dc, 3*Dc, 0, 1);
        gemm_h<<<dim3(2048/128, MBh), 256, GEMM_SMEM_H, s2>>>(
            xh + roff*Dc, wq_l + (size_t)1024*Dc, qb_l + 1024,
            qkvh + roff*3*Dc + 1024, Mh, 2048, Dc, 3*Dc, 0, 1);
        cudaEventRecord(eD1, s2);

        cudaStreamWaitEvent(0, eLn1, 0);
        cls_gatherx<<<Bc, 256>>>(x, cxc);
        cls_gemm<<<dim3(Bc, Dc/64), 256>>>(cxc, wq_l, qb_l, cqv, Dc, Dc, 0);

        cudaStreamWaitEvent(0, eD1, 0);
        cls_attn<<<Bc*Hc, 128>>>(qkvh, cqv, rel_l, mk, caf);

        const __half* wo_l = woh + (size_t)l*Dc*Dc;
        const __half* w1_l = w1h + (size_t)l*Dc*FFc;
        const __half* w2_l = w2h + (size_t)l*FFc*Dc;
        cls_gemm<<<dim3(Bc, Dc/64), 256>>>(caf, wo_l, out_b + (size_t)l*Dc, cty, Dc, Dc, 0);
        cls_ln<<<Bc, 256>>>(cxc, cty, ln1g + (size_t)l*Dc, ln1b + (size_t)l*Dc);
        cls_gemm<<<dim3(Bc, FFc/64), 256>>>(cxc, w1_l, l1b + (size_t)l*FFc, cth, FFc, Dc, 1);
        cls_gemm<<<dim3(Bc, Dc/64), 256>>>(cth, w2_l, l2b + (size_t)l*Dc, cty, Dc, FFc, 0);
        cls_ln<<<Bc, 256>>>(cxc, cty, ln2g + (size_t)l*Dc, ln2b + (size_t)l*Dc);
        cls_final<<<Bc, 256>>>(cxc, fng, fnb, clsw, clsb, (float*)d_out);
    }

    cudaEventDestroy(e0);
    cudaEventDestroy(ePrep);
    cudaEventDestroy(eLn1);
    cudaEventDestroy(eD1);
    for (int l = 0; l < NLc; l++) cudaEventDestroy(evW[l]);
    cudaStreamDestroy(s2);
    cudaStreamDestroy(s3);
}